// round 12
// baseline (speedup 1.0000x reference)
#include <cuda_runtime.h>
#include <cuda_fp16.h>
#include <cstdint>

#define D_DIM 128
#define K_DIM 32
#define MAXN  20000

// ---------------- device scratch (no allocation allowed) ----------------
__device__ float g_tsf[MAXN * D_DIM];                     // self_feats @ self_weights
__device__ float g_ts[MAXN];                              // self_vecs . gate_self_w
__device__ __align__(16) __half g_Wh[D_DIM * D_DIM];      // W^T fp16, [e][d] row-major

__device__ __forceinline__ float sigmoidf(float x) {
    return 1.0f / (1.0f + __expf(-x));
}

// fast sigmoid: 1 MUFU (tanh.approx), abs err ~3e-4
__device__ __forceinline__ float sigmoid_fast(float x) {
    float t;
    asm("tanh.approx.f32 %0, %1;" : "=f"(t) : "f"(0.5f * x));
    return fmaf(0.5f, t, 0.5f);
}

__device__ __forceinline__ uint32_t smem_u32(const void* p) {
    uint32_t a;
    asm("{ .reg .u64 t; cvta.to.shared.u64 t, %1; cvt.u32.u64 %0, t; }" : "=r"(a) : "l"(p));
    return a;
}

// packed f32x2 helpers (sm_100+ base PTX; exact rn fp32 semantics)
#define PACK2(dst, lo, hi) \
    asm("mov.b64 %0, {%1, %2};" : "=l"(dst) : "f"(lo), "f"(hi))
#define DUP2(dst, v) \
    asm("mov.b64 %0, {%1, %1};" : "=l"(dst) : "f"(v))
#define FMA2(acc, a, b) \
    asm("fma.rn.f32x2 %0, %1, %2, %0;" : "+l"(acc) : "l"(a), "l"(b))
#define UNPACK2(lo, hi, v) \
    asm("mov.b64 {%0, %1}, %2;" : "=f"(lo), "=f"(hi) : "l"(v))

#define MMA16816(cc, a0, a1, a2, a3, b0, b1)                                  \
    asm volatile(                                                             \
        "mma.sync.aligned.m16n8k16.row.col.f32.f16.f16.f32 "                  \
        "{%0,%1,%2,%3}, {%4,%5,%6,%7}, {%8,%9}, {%0,%1,%2,%3};"               \
        : "+f"((cc)[0]), "+f"((cc)[1]), "+f"((cc)[2]), "+f"((cc)[3])          \
        : "r"(a0), "r"(a1), "r"(a2), "r"(a3), "r"(b0), "r"(b1))

#define LDSM_X4(r, a)                                                         \
    asm volatile("ldmatrix.sync.aligned.m8n8.x4.shared.b16 {%0,%1,%2,%3}, [%4];" \
        : "=r"((r)[0]), "=r"((r)[1]), "=r"((r)[2]), "=r"((r)[3]) : "r"(a))

#define CP_ASYNC16(dst, src)                                                  \
    asm volatile("cp.async.ca.shared.global [%0], [%1], 16;" :: "r"(dst), "l"(src) : "memory")

// ---------------------------------------------------------------------------
// Kernel B: g_ts / g_tsf precompute (32 rows per block, 256 threads).
// Blocks 0..31 additionally transpose link_weights -> g_Wh (fused wh_kernel).
// GEMM inner loop: vectorized LDS + packed fma.rn.f32x2 (bit-exact fp32).
// ---------------------------------------------------------------------------
__global__ __launch_bounds__(256)
void precompute_kernel(const float* __restrict__ self_feats,
                       const float* __restrict__ self_vecs,
                       const float* __restrict__ gate_self_w,
                       const float* __restrict__ self_weights,
                       const float* __restrict__ link_weights,
                       int N) {
    __shared__ float As[32][D_DIM];
    __shared__ float gsw_s[D_DIM];

    const int tid = threadIdx.x;
    const int r0  = blockIdx.x * 32;

    // fused W^T fp16 conversion (first 32 blocks)
    if (blockIdx.x < 32) {
        int idx = blockIdx.x * 256 + tid;           // 0..8191
        int e  = idx >> 6;
        int d0 = (idx & 63) << 1;
        __half2 h = __floats2half2_rn(link_weights[(size_t)d0 * D_DIM + e],
                                      link_weights[(size_t)(d0 + 1) * D_DIM + e]);
        *(__half2*)(g_Wh + (size_t)e * D_DIM + d0) = h;
    }

    if (tid < 32)
        ((float4*)gsw_s)[tid] = ((const float4*)gate_self_w)[tid];

    for (int i = tid; i < 32 * 32; i += 256) {
        int r = i >> 5, c = i & 31;
        float4 v = make_float4(0.f, 0.f, 0.f, 0.f);
        if (r0 + r < N)
            v = ((const float4*)(self_feats + (size_t)(r0 + r) * D_DIM))[c];
        *(float4*)&As[r][c * 4] = v;
    }
    __syncthreads();

    const int w = tid >> 5, lane = tid & 31;
    for (int rr = w; rr < 32; rr += 8) {
        if (r0 + rr < N) {
            float4 v = ((const float4*)(self_vecs + (size_t)(r0 + rr) * D_DIM))[lane];
            float4 g = ((const float4*)gsw_s)[lane];
            float s = v.x * g.x + v.y * g.y + v.z * g.z + v.w * g.w;
            #pragma unroll
            for (int o = 16; o > 0; o >>= 1)
                s += __shfl_xor_sync(0xffffffffu, s, o);
            if (lane == 0) g_ts[r0 + rr] = s;
        }
    }

    // GEMM: 4 rows x 4 e-cols per thread, packed f32x2 accumulators
    const int tx = tid & 31, ty = tid >> 5;
    uint64_t acc01[4], acc23[4];
    #pragma unroll
    for (int i = 0; i < 4; i++) { acc01[i] = 0ull; acc23[i] = 0ull; }

    const float4* W4 = (const float4*)self_weights;
    for (int d0 = 0; d0 < D_DIM; d0 += 4) {
        float4 wv[4], a4[4];
        #pragma unroll
        for (int dd = 0; dd < 4; ++dd) wv[dd] = __ldg(&W4[(d0 + dd) * 32 + tx]);
        #pragma unroll
        for (int i = 0; i < 4; ++i) a4[i] = *(const float4*)&As[ty * 4 + i][d0];
        #pragma unroll
        for (int dd = 0; dd < 4; ++dd) {
            uint64_t w01, w23;
            PACK2(w01, wv[dd].x, wv[dd].y);
            PACK2(w23, wv[dd].z, wv[dd].w);
            #pragma unroll
            for (int i = 0; i < 4; ++i) {
                float a = (dd == 0) ? a4[i].x : (dd == 1) ? a4[i].y
                        : (dd == 2) ? a4[i].z : a4[i].w;
                uint64_t a2;
                DUP2(a2, a);
                FMA2(acc01[i], a2, w01);
                FMA2(acc23[i], a2, w23);
            }
        }
    }
    #pragma unroll
    for (int i = 0; i < 4; i++) {
        int r = ty * 4 + i;
        if (r0 + r < N) {
            float4 v;
            UNPACK2(v.x, v.y, acc01[i]);
            UNPACK2(v.z, v.w, acc23[i]);
            *(float4*)(g_tsf + (size_t)(r0 + r) * D_DIM + tx * 4) = v;
        }
    }
}

// ---------------------------------------------------------------------------
// Kernel C: persistent main kernel. 444 CTAs, 256 threads (8 warps) each,
// looping over node-pairs. W^T loaded into smem ONCE per CTA (cp.async).
//   Warp tile: 32 krows (ALL K of one node) x 32 e-cols, ldmatrix fragment
//   loads everywhere, k-reduction fully in-warp.
//   Ls [64 krow][136 half]  link fp16
//   Ns [64 krow][136 half]  neigh fp16
//   Wt [128 e  ][136 half]  W^T fp16
// ---------------------------------------------------------------------------
#define LPAD 68                        // row stride in u32 (136 halves, 272 B)
#define RSTB 272                       // row stride bytes
#define SM_GDP  0                      // 64 f
#define SM_LINK 256                    // 17408 B
#define SM_NEI  (256 + 17408)
#define SM_WT   (256 + 2 * 17408)      // 34816 B
#define SMEM_TOTAL (SM_WT + 34816)     // 69888 B
#define TC_GRID 444                    // 3 CTAs/SM x 148 SMs

__global__ __launch_bounds__(256, 3)
void tc_kernel(const float* __restrict__ neigh_vecs,
               const float* __restrict__ link_vecs,
               const float* __restrict__ select_probs,
               const float* __restrict__ gate_neigh_w,
               const float* __restrict__ gate_link_w,
               float* __restrict__ out, int N) {
    extern __shared__ char smem[];
    const uint32_t smem_base = smem_u32(smem);
    float*    gdp_s = (float*)(smem + SM_GDP);
    uint32_t* Lu    = (uint32_t*)(smem + SM_LINK);
    uint32_t* Nu    = (uint32_t*)(smem + SM_NEI);

    const int tid  = threadIdx.x;
    const int w    = tid >> 5;
    const int lane = tid & 31;

    // ---- W^T copy via cp.async: ONCE per CTA ----
    {
        const uint4* src = (const uint4*)g_Wh;
        #pragma unroll
        for (int i = 0; i < 8; ++i) {
            const int idx = i * 256 + tid;           // 0..2047 uint4
            const int r = idx >> 4, cb = (idx & 15) << 4;   // bytes within row
            uint32_t dst = smem_base + SM_WT + r * RSTB + cb;
            CP_ASYNC16(dst, src + idx);
        }
        asm volatile("cp.async.commit_group;" ::: "memory");
    }

    // ---- Loop-invariant index math ----
    const int r    = tid >> 2;           // CTA row 0..63 = node*32 + k
    const int h    = tid & 3;            // quarter-row
    const int nodeS = r >> 5, k = r & 31;

    const int node  = w >> 2;
    const int ecol0 = (w & 3) << 5;
    const int arow0 = node << 5;
    const int lane15 = lane & 15;
    const int sel16  = (lane >> 4) << 4;     // +16B for k-high matrices
    const int g = lane >> 2, t = lane & 3;

    const uint32_t aAddr0 = smem_base + SM_LINK + (arow0 + lane15) * RSTB + sel16;
    const uint32_t aAddr1 = aAddr0 + 16 * RSTB;
    const uint32_t bAddr0 = smem_base + SM_WT + (ecol0 + lane15) * RSTB + sel16;
    const uint32_t bAddr1 = bAddr0 + 16 * RSTB;
    const uint32_t nAddr  = smem_base + SM_NEI + (arow0 + lane15) * RSTB
                          + ecol0 * 2 + sel16;

    const float4* glw4 = (const float4*)gate_link_w;
    const float4* gnw4 = (const float4*)gate_neigh_w;

    const int npairs = (N + 1) >> 1;

    for (int pair = blockIdx.x; pair < npairs; pair += gridDim.x) {
        // ---- Stage: gates + link/neigh fp32->fp16 into padded smem ----
        {
            const size_t ng = (size_t)pair * 2 + nodeS;
            const bool valid = (ng < (size_t)N);

            const float4* lrow = (const float4*)(link_vecs  + ((size_t)ng * K_DIM + k) * D_DIM);
            const float4* nrow = (const float4*)(neigh_vecs + ((size_t)ng * K_DIM + k) * D_DIM);
            uint64_t dl2 = 0ull, dn2 = 0ull;
            if (valid) {
                #pragma unroll
                for (int j = 0; j < 8; ++j) {
                    const int f4 = j * 4 + h;            // float4 index 0..31
                    const int cu = f4 * 2;               // u32 col 0..62
                    float4 v = lrow[f4];
                    float4 gg = __ldg(&glw4[f4]);
                    uint64_t vxy, vzw, gxy, gzw;
                    PACK2(vxy, v.x, v.y); PACK2(vzw, v.z, v.w);
                    PACK2(gxy, gg.x, gg.y); PACK2(gzw, gg.z, gg.w);
                    FMA2(dl2, vxy, gxy);
                    FMA2(dl2, vzw, gzw);
                    __half2 p0 = __floats2half2_rn(v.x, v.y);
                    __half2 p1 = __floats2half2_rn(v.z, v.w);
                    *(uint2*)&Lu[r * LPAD + cu] = make_uint2(*(uint32_t*)&p0, *(uint32_t*)&p1);

                    float4 nv = nrow[f4];
                    float4 gn = __ldg(&gnw4[f4]);
                    uint64_t nxy, nzw, hxy, hzw;
                    PACK2(nxy, nv.x, nv.y); PACK2(nzw, nv.z, nv.w);
                    PACK2(hxy, gn.x, gn.y); PACK2(hzw, gn.z, gn.w);
                    FMA2(dn2, nxy, hxy);
                    FMA2(dn2, nzw, hzw);
                    __half2 q0 = __floats2half2_rn(nv.x, nv.y);
                    __half2 q1 = __floats2half2_rn(nv.z, nv.w);
                    *(uint2*)&Nu[r * LPAD + cu] = make_uint2(*(uint32_t*)&q0, *(uint32_t*)&q1);
                }
            }
            float dlo, dhi, dl, dn;
            UNPACK2(dlo, dhi, dl2); dl = dlo + dhi;
            UNPACK2(dlo, dhi, dn2); dn = dlo + dhi;
            dl += __shfl_xor_sync(0xffffffffu, dl, 1);
            dl += __shfl_xor_sync(0xffffffffu, dl, 2);
            dn += __shfl_xor_sync(0xffffffffu, dn, 1);
            dn += __shfl_xor_sync(0xffffffffu, dn, 2);
            if (h == 0 && valid) {
                float ts = g_ts[ng];
                float p  = select_probs[ng * K_DIM + k];
                gdp_s[r] = sigmoidf(ts + dl + dn) / ((float)K_DIM * p);
            }
        }

        asm volatile("cp.async.wait_group 0;" ::: "memory");
        __syncthreads();

        // ---- GEMM: warp w -> node (w>>2), e-cols [(w&3)*32, +32) ----
        float c[2][4][4];
        #pragma unroll
        for (int mt = 0; mt < 2; ++mt)
            #pragma unroll
            for (int nt = 0; nt < 4; ++nt)
                #pragma unroll
                for (int j = 0; j < 4; ++j) c[mt][nt][j] = 0.f;

        #pragma unroll
        for (int ks = 0; ks < 8; ++ks) {
            const uint32_t koff = ks * 32;       // 16 halves per k-step
            uint32_t a0[4], a1[4], b0[4], b1[4];
            LDSM_X4(a0, aAddr0 + koff);          // rows arow0..+15
            LDSM_X4(a1, aAddr1 + koff);          // rows arow0+16..+31
            LDSM_X4(b0, bAddr0 + koff);          // {nt0 klo, nt1 klo, nt0 khi, nt1 khi}
            LDSM_X4(b1, bAddr1 + koff);          // nt2, nt3
            MMA16816(c[0][0], a0[0], a0[1], a0[2], a0[3], b0[0], b0[2]);
            MMA16816(c[0][1], a0[0], a0[1], a0[2], a0[3], b0[1], b0[3]);
            MMA16816(c[0][2], a0[0], a0[1], a0[2], a0[3], b1[0], b1[2]);
            MMA16816(c[0][3], a0[0], a0[1], a0[2], a0[3], b1[1], b1[3]);
            MMA16816(c[1][0], a1[0], a1[1], a1[2], a1[3], b0[0], b0[2]);
            MMA16816(c[1][1], a1[0], a1[1], a1[2], a1[3], b0[1], b0[3]);
            MMA16816(c[1][2], a1[0], a1[1], a1[2], a1[3], b1[0], b1[2]);
            MMA16816(c[1][3], a1[0], a1[1], a1[2], a1[3], b1[1], b1[3]);
        }

        // ---- Epilogue: sigmoid * neigh * gdp, full k-sum in-warp, store ----
        {
            const size_t ng = (size_t)pair * 2 + node;
            if (ng < (size_t)N) {
                float p0[4] = {0.f, 0.f, 0.f, 0.f};
                float p1[4] = {0.f, 0.f, 0.f, 0.f};

                #pragma unroll
                for (int mt = 0; mt < 2; ++mt) {
                    const int r0 = arow0 + mt * 16 + g;
                    const float gd0 = gdp_s[r0];
                    const float gd1 = gdp_s[r0 + 8];
                    uint32_t nA[4], nB[4];
                    LDSM_X4(nA, nAddr + mt * 16 * RSTB);        // nt0, nt1
                    LDSM_X4(nB, nAddr + mt * 16 * RSTB + 32);   // nt2, nt3
                    #pragma unroll
                    for (int nt = 0; nt < 4; ++nt) {
                        uint32_t u0 = (nt < 2) ? nA[nt * 2]     : nB[(nt - 2) * 2];
                        uint32_t u1 = (nt < 2) ? nA[nt * 2 + 1] : nB[(nt - 2) * 2 + 1];
                        float2 n0 = __half22float2(*(__half2*)&u0);
                        float2 n1 = __half22float2(*(__half2*)&u1);
                        p0[nt] += sigmoid_fast(c[mt][nt][0]) * n0.x * gd0
                                + sigmoid_fast(c[mt][nt][2]) * n1.x * gd1;
                        p1[nt] += sigmoid_fast(c[mt][nt][1]) * n0.y * gd0
                                + sigmoid_fast(c[mt][nt][3]) * n1.y * gd1;
                    }
                }
                #pragma unroll
                for (int nt = 0; nt < 4; ++nt) {
                    #pragma unroll
                    for (int o = 4; o < 32; o <<= 1) {
                        p0[nt] += __shfl_xor_sync(0xffffffffu, p0[nt], o);
                        p1[nt] += __shfl_xor_sync(0xffffffffu, p1[nt], o);
                    }
                }
                if (g == 0) {
                    #pragma unroll
                    for (int nt = 0; nt < 4; ++nt) {
                        const int col = ecol0 + nt * 8 + 2 * t;
                        float2 tf = *(const float2*)(g_tsf + ng * D_DIM + col);
                        float2 o2;
                        o2.x = fmaxf(p0[nt] * tf.x, 0.f);
                        o2.y = fmaxf(p1[nt] * tf.y, 0.f);
                        *(float2*)(out + ng * D_DIM + col) = o2;
                    }
                }
            }
        }

        // protect Lu/Nu/gdp_s before next iteration's stage overwrites them
        __syncthreads();
    }
}

// ---------------------------------------------------------------------------
extern "C" void kernel_launch(void* const* d_in, const int* in_sizes, int n_in,
                              void* d_out, int out_size) {
    const float* self_feats   = (const float*)d_in[0];
    const float* self_vecs    = (const float*)d_in[1];
    const float* neigh_vecs   = (const float*)d_in[2];
    const float* link_vecs    = (const float*)d_in[3];
    const float* select_probs = (const float*)d_in[4];
    const float* gate_self_w  = (const float*)d_in[5];
    const float* gate_neigh_w = (const float*)d_in[6];
    const float* gate_link_w  = (const float*)d_in[7];
    const float* self_weights = (const float*)d_in[8];
    const float* link_weights = (const float*)d_in[9];
    float* out = (float*)d_out;

    const int N = in_sizes[0] / D_DIM;

    static bool attr_set = false;
    if (!attr_set) {
        cudaFuncSetAttribute(tc_kernel, cudaFuncAttributeMaxDynamicSharedMemorySize,
                             SMEM_TOTAL);
        attr_set = true;
    }

    int pre_grid = (N + 31) / 32;
    if (pre_grid < 32) pre_grid = 32;
    precompute_kernel<<<pre_grid, 256>>>(self_feats, self_vecs, gate_self_w,
                                         self_weights, link_weights, N);

    int npairs = (N + 1) / 2;
    int tc_grid = npairs < TC_GRID ? npairs : TC_GRID;
    tc_kernel<<<tc_grid, 256, SMEM_TOTAL>>>(neigh_vecs, link_vecs, select_probs,
                                            gate_neigh_w, gate_link_w, out, N);
}